// round 6
// baseline (speedup 1.0000x reference)
#include <cuda_runtime.h>
#include <math.h>

// Transposed intermediate: all_feat_T[row][b], row in [0,208), B = 65536.
static __device__ float g_allfeat[208u * 65536u];

#define HIS 5
#define KINDS 10

__device__ __forceinline__ float4 ldg4(const float* p) {
    return __ldg((const float4*)p);
}

__device__ __forceinline__ void store8(int B, int b, int row, float4 v0, float4 v1) {
    float* p = g_allfeat + (size_t)row * (size_t)B + (size_t)b;
    size_t s = (size_t)B;
    p[0]     = v0.x; p[s]     = v0.y; p[2*s]   = v0.z; p[3*s]   = v0.w;
    p[4*s]   = v1.x; p[5*s]   = v1.y; p[6*s]   = v1.z; p[7*s]   = v1.w;
}

// ---------------------------------------------------------------------------
// Kernel 1: gathers + ActUnit (Wa/Wc decomposition) + his_pool,
// writes transposed all_feat[208][B].
// ---------------------------------------------------------------------------
extern "C" __global__ void __launch_bounds__(128, 2)
k1_act(const int* __restrict__ userid, const int* __restrict__ itemid,
       const int* __restrict__ user_age, const int* __restrict__ gender,
       const int* __restrict__ user_occ,
       const int* __restrict__ item_kind, const int* __restrict__ his_id,
       const int* __restrict__ his_kind,
       const float* __restrict__ user_emb, const float* __restrict__ item_emb,
       const float* __restrict__ age_emb, const float* __restrict__ gender_emb,
       const float* __restrict__ occ_emb, const float* __restrict__ kind_emb,
       const float* __restrict__ act_w1, const float* __restrict__ act_b1,
       const float* __restrict__ act_w2, const float* __restrict__ act_b2,
       const float* __restrict__ act_w3, const float* __restrict__ act_b3,
       int B)
{
    __shared__ float sWa[64 * 88];   // W1[:,0:88] + W1[:,88:176]
    __shared__ float sWc[64 * 88];   // W1[:,176:264] - W1[:,88:176]
    __shared__ float sB1[64];
    __shared__ float sB2[32];
    __shared__ float sW3[32];
    __shared__ float sB3s;

    for (int idx = threadIdx.x; idx < 64 * 88; idx += blockDim.x) {
        int o = idx / 88, k = idx - o * 88;
        const float* r = act_w1 + o * 264;
        float wb = r[88 + k];
        sWa[idx] = r[k] + wb;
        sWc[idx] = r[176 + k] - wb;
    }
    if (threadIdx.x < 64) sB1[threadIdx.x] = act_b1[threadIdx.x];
    if (threadIdx.x < 32) { sB2[threadIdx.x] = act_b2[threadIdx.x];
                            sW3[threadIdx.x] = act_w3[threadIdx.x]; }
    if (threadIdx.x == 0) sB3s = act_b3[0];
    __syncthreads();

    int b = blockIdx.x * blockDim.x + threadIdx.x;
    if (b >= B) return;

    // ---- simple feature rows: user(0:8), age(16:24), gender(24:32), occ(32:40)
    {
        const float* p = user_emb + (size_t)userid[b] * 8;
        store8(B, b, 0, ldg4(p), ldg4(p + 4));
        p = age_emb + (size_t)user_age[b] * 8;
        store8(B, b, 16, ldg4(p), ldg4(p + 4));
        p = gender_emb + (size_t)gender[b] * 8;
        store8(B, b, 24, ldg4(p), ldg4(p + 4));
        p = occ_emb + (size_t)user_occ[b] * 8;
        store8(B, b, 32, ldg4(p), ldg4(p + 4));
    }

    // ---- base = b1 + Wc @ i2 ; also write item(8:16) and kind(40:120) rows
    float base[64];
    #pragma unroll
    for (int o = 0; o < 64; o++) base[o] = sB1[o];

    int iid = itemid[b];
    #pragma unroll 1
    for (int j = 0; j < 11; j++) {
        float4 v0, v1;
        int row;
        if (j == 0) {
            const float* p = item_emb + (size_t)iid * 8;
            v0 = ldg4(p); v1 = ldg4(p + 4);
            row = 8;
        } else {
            int kk = item_kind[b * KINDS + (j - 1)];
            const float* p = kind_emb + (size_t)kk * 8;
            v0 = ldg4(p); v1 = ldg4(p + 4);
            if (kk == 0) { v0 = make_float4(0.f,0.f,0.f,0.f); v1 = v0; }
            row = 40 + 8 * (j - 1);
        }
        store8(B, b, row, v0, v1);
        const float* wb = sWc + j * 8;
        #pragma unroll
        for (int o = 0; o < 64; o++) {
            float4 w0 = *(const float4*)(wb + o * 88);
            float4 w1 = *(const float4*)(wb + o * 88 + 4);
            base[o] += w0.x*v0.x + w0.y*v0.y + w0.z*v0.z + w0.w*v0.w
                     + w1.x*v1.x + w1.y*v1.y + w1.z*v1.z + w1.w*v1.w;
        }
    }

    // ---- pass 1: attention scores per history slot
    float scoresL[HIS];
    #pragma unroll 1
    for (int s = 0; s < HIS; s++) {
        float acc[64];
        #pragma unroll
        for (int o = 0; o < 64; o++) acc[o] = base[o];

        int hid = his_id[b * HIS + s];
        #pragma unroll 1
        for (int j = 0; j < 11; j++) {
            float4 v0, v1;
            if (j == 0) {
                const float* p = item_emb + (size_t)hid * 8;
                v0 = ldg4(p); v1 = ldg4(p + 4);
            } else {
                int kk = his_kind[(b * HIS + s) * KINDS + (j - 1)];
                const float* p = kind_emb + (size_t)kk * 8;
                v0 = ldg4(p); v1 = ldg4(p + 4);
                if (kk == 0) { v0 = make_float4(0.f,0.f,0.f,0.f); v1 = v0; }
            }
            const float* wb = sWa + j * 8;
            #pragma unroll
            for (int o = 0; o < 64; o++) {
                float4 w0 = *(const float4*)(wb + o * 88);
                float4 w1 = *(const float4*)(wb + o * 88 + 4);
                acc[o] += w0.x*v0.x + w0.y*v0.y + w0.z*v0.z + w0.w*v0.w
                        + w1.x*v1.x + w1.y*v1.y + w1.z*v1.z + w1.w*v1.w;
            }
        }

        float h1l[64];
        #pragma unroll
        for (int o = 0; o < 64; o++) h1l[o] = fmaxf(acc[o], 0.f);

        float acc2[32];
        #pragma unroll
        for (int o = 0; o < 32; o++) acc2[o] = sB2[o];
        #pragma unroll 1
        for (int kc = 0; kc < 16; kc++) {
            float a0 = h1l[4*kc+0], a1 = h1l[4*kc+1];
            float a2 = h1l[4*kc+2], a3 = h1l[4*kc+3];
            const float* wb = act_w2 + 4 * kc;  // warp-uniform L1-cached LDG
            #pragma unroll
            for (int o = 0; o < 32; o++) {
                float4 w = ldg4(wb + o * 64);
                acc2[o] += w.x*a0 + w.y*a1 + w.z*a2 + w.w*a3;
            }
        }
        float sc = sB3s;
        #pragma unroll
        for (int o = 0; o < 32; o++) sc += sW3[o] * fmaxf(acc2[o], 0.f);
        scoresL[s] = sc;
    }

    // ---- pass 2: his_pool[d] = sum_s i1[s][d]^2 * score[s]  (re-gather i1)
    float poolL[88];
    #pragma unroll 1
    for (int d = 0; d < 88; d++) poolL[d] = 0.f;

    #pragma unroll 1
    for (int s = 0; s < HIS; s++) {
        float sc = scoresL[s];
        int hid = his_id[b * HIS + s];
        #pragma unroll 1
        for (int j = 0; j < 11; j++) {
            float4 v0, v1;
            if (j == 0) {
                const float* p = item_emb + (size_t)hid * 8;
                v0 = ldg4(p); v1 = ldg4(p + 4);
            } else {
                int kk = his_kind[(b * HIS + s) * KINDS + (j - 1)];
                const float* p = kind_emb + (size_t)kk * 8;
                v0 = ldg4(p); v1 = ldg4(p + 4);
                if (kk == 0) { v0 = make_float4(0.f,0.f,0.f,0.f); v1 = v0; }
            }
            int pp = j * 8;
            poolL[pp+0] += v0.x*v0.x*sc; poolL[pp+1] += v0.y*v0.y*sc;
            poolL[pp+2] += v0.z*v0.z*sc; poolL[pp+3] += v0.w*v0.w*sc;
            poolL[pp+4] += v1.x*v1.x*sc; poolL[pp+5] += v1.y*v1.y*sc;
            poolL[pp+6] += v1.z*v1.z*sc; poolL[pp+7] += v1.w*v1.w*sc;
        }
    }
    #pragma unroll 1
    for (int d = 0; d < 88; d++)
        g_allfeat[(size_t)(120 + d) * (size_t)B + (size_t)b] = poolL[d];
}

// ---------------------------------------------------------------------------
// Kernel 2: MLP 208->128->64->32->1 + sigmoid.
// ---------------------------------------------------------------------------
extern "C" __global__ void __launch_bounds__(128, 2)
k2_mlp(const float* __restrict__ mlp_w1, const float* __restrict__ mlp_b1,
       const float* __restrict__ mlp_w2, const float* __restrict__ mlp_b2,
       const float* __restrict__ mlp_w3, const float* __restrict__ mlp_b3,
       const float* __restrict__ mlp_w4, const float* __restrict__ mlp_b4,
       float* __restrict__ out, int B)
{
    __shared__ float sW2[64 * 128];
    __shared__ float sW3[32 * 64];
    __shared__ float sW4[32];
    __shared__ float sB1[128];
    __shared__ float sB2[64];
    __shared__ float sB3[32];
    __shared__ float sB4s;

    for (int idx = threadIdx.x; idx < 64 * 128; idx += blockDim.x) sW2[idx] = mlp_w2[idx];
    for (int idx = threadIdx.x; idx < 32 * 64;  idx += blockDim.x) sW3[idx] = mlp_w3[idx];
    if (threadIdx.x < 128) sB1[threadIdx.x] = mlp_b1[threadIdx.x];
    if (threadIdx.x < 64)  sB2[threadIdx.x] = mlp_b2[threadIdx.x];
    if (threadIdx.x < 32)  { sB3[threadIdx.x] = mlp_b3[threadIdx.x];
                             sW4[threadIdx.x] = mlp_w4[threadIdx.x]; }
    if (threadIdx.x == 0) sB4s = mlp_b4[0];
    __syncthreads();

    int b = blockIdx.x * blockDim.x + threadIdx.x;
    if (b >= B) return;

    size_t sB = (size_t)B;

    float acc1[128];
    #pragma unroll
    for (int o = 0; o < 128; o++) acc1[o] = sB1[o];

    #pragma unroll 1
    for (int dc = 0; dc < 52; dc++) {   // 208 / 4
        const float* col = g_allfeat + (size_t)(4 * dc) * sB + (size_t)b;
        float a0 = col[0];
        float a1 = col[sB];
        float a2 = col[2 * sB];
        float a3 = col[3 * sB];
        const float* w1b = mlp_w1 + 4 * dc;
        #pragma unroll
        for (int o = 0; o < 128; o++) {
            float4 w = ldg4(w1b + o * 208);
            acc1[o] += w.x*a0 + w.y*a1 + w.z*a2 + w.w*a3;
        }
    }

    float h1l[128];
    #pragma unroll
    for (int o = 0; o < 128; o++) h1l[o] = fmaxf(acc1[o], 0.f);

    float acc2[64];
    #pragma unroll
    for (int o = 0; o < 64; o++) acc2[o] = sB2[o];
    #pragma unroll 1
    for (int kc = 0; kc < 32; kc++) {
        float a0 = h1l[4*kc+0], a1 = h1l[4*kc+1];
        float a2 = h1l[4*kc+2], a3 = h1l[4*kc+3];
        const float* wb = sW2 + 4 * kc;
        #pragma unroll
        for (int o = 0; o < 64; o++) {
            float4 w = *(const float4*)(wb + o * 128);
            acc2[o] += w.x*a0 + w.y*a1 + w.z*a2 + w.w*a3;
        }
    }

    float h2l[64];
    #pragma unroll
    for (int o = 0; o < 64; o++) h2l[o] = fmaxf(acc2[o], 0.f);

    float acc3[32];
    #pragma unroll
    for (int o = 0; o < 32; o++) acc3[o] = sB3[o];
    #pragma unroll 1
    for (int kc = 0; kc < 16; kc++) {
        float a0 = h2l[4*kc+0], a1 = h2l[4*kc+1];
        float a2 = h2l[4*kc+2], a3 = h2l[4*kc+3];
        const float* wb = sW3 + 4 * kc;
        #pragma unroll
        for (int o = 0; o < 32; o++) {
            float4 w = *(const float4*)(wb + o * 64);
            acc3[o] += w.x*a0 + w.y*a1 + w.z*a2 + w.w*a3;
        }
    }

    float logit = sB4s;
    #pragma unroll
    for (int o = 0; o < 32; o++) logit += sW4[o] * fmaxf(acc3[o], 0.f);

    out[b] = 1.f / (1.f + expf(-logit));
}

// ---------------------------------------------------------------------------
extern "C" void kernel_launch(void* const* d_in, const int* in_sizes, int n_in,
                              void* d_out, int out_size)
{
    const int*   userid   = (const int*)d_in[0];
    const int*   itemid   = (const int*)d_in[1];
    const int*   user_age = (const int*)d_in[2];
    const int*   gender   = (const int*)d_in[3];
    const int*   user_occ = (const int*)d_in[4];
    const int*   item_kind= (const int*)d_in[5];
    const int*   his_id   = (const int*)d_in[6];
    const int*   his_kind = (const int*)d_in[7];
    const float* user_emb = (const float*)d_in[8];
    const float* item_emb = (const float*)d_in[9];
    const float* age_emb  = (const float*)d_in[10];
    const float* gen_emb  = (const float*)d_in[11];
    const float* occ_emb  = (const float*)d_in[12];
    const float* kind_emb = (const float*)d_in[13];
    const float* act_w1 = (const float*)d_in[14];
    const float* act_b1 = (const float*)d_in[15];
    const float* act_w2 = (const float*)d_in[16];
    const float* act_b2 = (const float*)d_in[17];
    const float* act_w3 = (const float*)d_in[18];
    const float* act_b3 = (const float*)d_in[19];
    const float* mlp_w1 = (const float*)d_in[20];
    const float* mlp_b1 = (const float*)d_in[21];
    const float* mlp_w2 = (const float*)d_in[22];
    const float* mlp_b2 = (const float*)d_in[23];
    const float* mlp_w3 = (const float*)d_in[24];
    const float* mlp_b3 = (const float*)d_in[25];
    const float* mlp_w4 = (const float*)d_in[26];
    const float* mlp_b4 = (const float*)d_in[27];

    int B = in_sizes[0];   // userid is (B,1)
    int blocks = (B + 127) / 128;

    k1_act<<<blocks, 128>>>(userid, itemid, user_age, gender, user_occ,
                            item_kind, his_id, his_kind,
                            user_emb, item_emb, age_emb, gen_emb, occ_emb, kind_emb,
                            act_w1, act_b1, act_w2, act_b2, act_w3, act_b3, B);

    k2_mlp<<<blocks, 128>>>(mlp_w1, mlp_b1, mlp_w2, mlp_b2,
                            mlp_w3, mlp_b3, mlp_w4, mlp_b4,
                            (float*)d_out, B);
}

// round 7
// speedup vs baseline: 1.4423x; 1.4423x over previous
#include <cuda_runtime.h>
#include <math.h>

#define BMAX 65536
#define HIS 5
#define KINDS 10

// Pair-packed transposed scratch: X2[row_pair][b], row_pair = scalar_row/2.
static __device__ float2 g_allfeat2[104u * BMAX];  // 208 scalar rows
static __device__ float2 g_base2[32u * BMAX];      // 64 scalar rows
static __device__ float2 g_h12[64u * BMAX];        // 128 scalar rows
static __device__ float  g_score[HIS * BMAX];

__device__ __forceinline__ float4 ldg4(const float* p) {
    return __ldg((const float4*)p);
}

// store 8 consecutive scalar rows (row even) of all_feat for sample b
__device__ __forceinline__ void store8(int B, int b, int row, float4 v0, float4 v1) {
    float2* p = g_allfeat2 + (size_t)(row >> 1) * (size_t)B + (size_t)b;
    size_t s = (size_t)B;
    p[0]   = make_float2(v0.x, v0.y);
    p[s]   = make_float2(v0.z, v0.w);
    p[2*s] = make_float2(v1.x, v1.y);
    p[3*s] = make_float2(v1.z, v1.w);
}

// ---------------------------------------------------------------------------
// k0: embedding gathers for non-history features + base = b1 + Wc @ i2.
// Writes all_feat rows 0..119 and g_base.
// ---------------------------------------------------------------------------
extern "C" __global__ void __launch_bounds__(128, 4)
k0_feat(const int* __restrict__ userid, const int* __restrict__ itemid,
        const int* __restrict__ user_age, const int* __restrict__ gender,
        const int* __restrict__ user_occ, const int* __restrict__ item_kind,
        const float* __restrict__ user_emb, const float* __restrict__ item_emb,
        const float* __restrict__ age_emb, const float* __restrict__ gender_emb,
        const float* __restrict__ occ_emb, const float* __restrict__ kind_emb,
        const float* __restrict__ act_w1, const float* __restrict__ act_b1,
        int B)
{
    __shared__ float sWc[64 * 88];   // W1[:,176:264] - W1[:,88:176]
    __shared__ float sB1[64];

    for (int idx = threadIdx.x; idx < 64 * 88; idx += blockDim.x) {
        int o = idx / 88, k = idx - o * 88;
        const float* r = act_w1 + o * 264;
        sWc[idx] = r[176 + k] - r[88 + k];
    }
    if (threadIdx.x < 64) sB1[threadIdx.x] = act_b1[threadIdx.x];
    __syncthreads();

    int b = blockIdx.x * blockDim.x + threadIdx.x;
    if (b >= B) return;

    // simple rows: user(0), age(16), gender(24), occ(32)
    {
        const float* p = user_emb + (size_t)userid[b] * 8;
        store8(B, b, 0, ldg4(p), ldg4(p + 4));
        p = age_emb + (size_t)user_age[b] * 8;
        store8(B, b, 16, ldg4(p), ldg4(p + 4));
        p = gender_emb + (size_t)gender[b] * 8;
        store8(B, b, 24, ldg4(p), ldg4(p + 4));
        p = occ_emb + (size_t)user_occ[b] * 8;
        store8(B, b, 32, ldg4(p), ldg4(p + 4));
    }

    float base[64];
    #pragma unroll
    for (int o = 0; o < 64; o++) base[o] = sB1[o];

    int iid = itemid[b];
    #pragma unroll 1
    for (int j = 0; j < 11; j++) {
        float4 v0, v1;
        int row;
        if (j == 0) {
            const float* p = item_emb + (size_t)iid * 8;
            v0 = ldg4(p); v1 = ldg4(p + 4);
            row = 8;
        } else {
            int kk = item_kind[b * KINDS + (j - 1)];
            const float* p = kind_emb + (size_t)kk * 8;
            v0 = ldg4(p); v1 = ldg4(p + 4);
            if (kk == 0) { v0 = make_float4(0.f,0.f,0.f,0.f); v1 = v0; }
            row = 40 + 8 * (j - 1);
        }
        store8(B, b, row, v0, v1);
        const float* wb = sWc + j * 8;
        #pragma unroll
        for (int o = 0; o < 64; o++) {
            float4 w0 = *(const float4*)(wb + o * 88);
            float4 w1 = *(const float4*)(wb + o * 88 + 4);
            base[o] += w0.x*v0.x + w0.y*v0.y + w0.z*v0.z + w0.w*v0.w
                     + w1.x*v1.x + w1.y*v1.y + w1.z*v1.z + w1.w*v1.w;
        }
    }

    float2* bp = g_base2 + (size_t)b;
    size_t sB = (size_t)B;
    #pragma unroll
    for (int o = 0; o < 32; o++)
        bp[(size_t)o * sB] = make_float2(base[2*o], base[2*o + 1]);
}

// ---------------------------------------------------------------------------
// k1: attention score for history slot s = blockIdx.y.
// acc = base + Wa @ i1[s]; then 64->32->1.
// ---------------------------------------------------------------------------
extern "C" __global__ void __launch_bounds__(128, 4)
k1_score(const int* __restrict__ his_id, const int* __restrict__ his_kind,
         const float* __restrict__ item_emb, const float* __restrict__ kind_emb,
         const float* __restrict__ act_w1,
         const float* __restrict__ act_w2, const float* __restrict__ act_b2,
         const float* __restrict__ act_w3, const float* __restrict__ act_b3,
         int B)
{
    __shared__ float sWa[64 * 88];   // W1[:,0:88] + W1[:,88:176]
    __shared__ float sW2[32 * 64];
    __shared__ float sB2[32];
    __shared__ float sW3[32];
    __shared__ float sB3s;

    for (int idx = threadIdx.x; idx < 64 * 88; idx += blockDim.x) {
        int o = idx / 88, k = idx - o * 88;
        const float* r = act_w1 + o * 264;
        sWa[idx] = r[k] + r[88 + k];
    }
    for (int idx = threadIdx.x; idx < 32 * 64; idx += blockDim.x) sW2[idx] = act_w2[idx];
    if (threadIdx.x < 32) { sB2[threadIdx.x] = act_b2[threadIdx.x];
                            sW3[threadIdx.x] = act_w3[threadIdx.x]; }
    if (threadIdx.x == 0) sB3s = act_b3[0];
    __syncthreads();

    int b = blockIdx.x * blockDim.x + threadIdx.x;
    if (b >= B) return;
    int s = blockIdx.y;
    size_t sB = (size_t)B;

    float acc[64];
    {
        const float2* bp = g_base2 + (size_t)b;
        #pragma unroll
        for (int o = 0; o < 32; o++) {
            float2 v = bp[(size_t)o * sB];
            acc[2*o] = v.x; acc[2*o + 1] = v.y;
        }
    }

    int hid = his_id[b * HIS + s];
    #pragma unroll 1
    for (int j = 0; j < 11; j++) {
        float4 v0, v1;
        if (j == 0) {
            const float* p = item_emb + (size_t)hid * 8;
            v0 = ldg4(p); v1 = ldg4(p + 4);
        } else {
            int kk = his_kind[(b * HIS + s) * KINDS + (j - 1)];
            const float* p = kind_emb + (size_t)kk * 8;
            v0 = ldg4(p); v1 = ldg4(p + 4);
            if (kk == 0) { v0 = make_float4(0.f,0.f,0.f,0.f); v1 = v0; }
        }
        const float* wb = sWa + j * 8;
        #pragma unroll
        for (int o = 0; o < 64; o++) {
            float4 w0 = *(const float4*)(wb + o * 88);
            float4 w1 = *(const float4*)(wb + o * 88 + 4);
            acc[o] += w0.x*v0.x + w0.y*v0.y + w0.z*v0.z + w0.w*v0.w
                    + w1.x*v1.x + w1.y*v1.y + w1.z*v1.z + w1.w*v1.w;
        }
    }

    float h1l[64];   // spilled to L1-local by the dynamic kc reads below
    #pragma unroll
    for (int o = 0; o < 64; o++) h1l[o] = fmaxf(acc[o], 0.f);

    float acc2[32];
    #pragma unroll
    for (int o = 0; o < 32; o++) acc2[o] = sB2[o];
    #pragma unroll 1
    for (int kc = 0; kc < 16; kc++) {
        float a0 = h1l[4*kc+0], a1 = h1l[4*kc+1];
        float a2 = h1l[4*kc+2], a3 = h1l[4*kc+3];
        const float* wb = sW2 + 4 * kc;
        #pragma unroll
        for (int o = 0; o < 32; o++) {
            float4 w = *(const float4*)(wb + o * 64);
            acc2[o] += w.x*a0 + w.y*a1 + w.z*a2 + w.w*a3;
        }
    }
    float sc = sB3s;
    #pragma unroll
    for (int o = 0; o < 32; o++) sc += sW3[o] * fmaxf(acc2[o], 0.f);
    g_score[(size_t)s * sB + (size_t)b] = sc;
}

// ---------------------------------------------------------------------------
// k2: his_pool[d] = sum_s i1[s][d]^2 * score[s]; writes rows 120..207.
// ---------------------------------------------------------------------------
extern "C" __global__ void __launch_bounds__(128, 4)
k2_pool(const int* __restrict__ his_id, const int* __restrict__ his_kind,
        const float* __restrict__ item_emb, const float* __restrict__ kind_emb,
        int B)
{
    int b = blockIdx.x * blockDim.x + threadIdx.x;
    if (b >= B) return;
    size_t sB = (size_t)B;

    float poolL[88];
    #pragma unroll 1
    for (int d = 0; d < 88; d++) poolL[d] = 0.f;

    #pragma unroll 1
    for (int s = 0; s < HIS; s++) {
        float sc = g_score[(size_t)s * sB + (size_t)b];
        int hid = his_id[b * HIS + s];
        #pragma unroll 1
        for (int j = 0; j < 11; j++) {
            float4 v0, v1;
            if (j == 0) {
                const float* p = item_emb + (size_t)hid * 8;
                v0 = ldg4(p); v1 = ldg4(p + 4);
            } else {
                int kk = his_kind[(b * HIS + s) * KINDS + (j - 1)];
                const float* p = kind_emb + (size_t)kk * 8;
                v0 = ldg4(p); v1 = ldg4(p + 4);
                if (kk == 0) { v0 = make_float4(0.f,0.f,0.f,0.f); v1 = v0; }
            }
            int pp = j * 8;
            poolL[pp+0] += v0.x*v0.x*sc; poolL[pp+1] += v0.y*v0.y*sc;
            poolL[pp+2] += v0.z*v0.z*sc; poolL[pp+3] += v0.w*v0.w*sc;
            poolL[pp+4] += v1.x*v1.x*sc; poolL[pp+5] += v1.y*v1.y*sc;
            poolL[pp+6] += v1.z*v1.z*sc; poolL[pp+7] += v1.w*v1.w*sc;
        }
    }
    float2* p = g_allfeat2 + (size_t)60 * sB + (size_t)b;   // scalar row 120
    #pragma unroll 1
    for (int d = 0; d < 44; d++)
        p[(size_t)d * sB] = make_float2(poolL[2*d], poolL[2*d + 1]);
}

// ---------------------------------------------------------------------------
// k3: h1 = relu(mlp_w1 @ all_feat + b1), output chunk c = blockIdx.y (32 rows).
// ---------------------------------------------------------------------------
extern "C" __global__ void __launch_bounds__(128, 4)
k3_h1(const float* __restrict__ mlp_w1, const float* __restrict__ mlp_b1, int B)
{
    int b = blockIdx.x * blockDim.x + threadIdx.x;
    if (b >= B) return;
    int c = blockIdx.y;            // output rows [32c, 32c+32)
    size_t sB = (size_t)B;

    float acc[32];
    #pragma unroll
    for (int o = 0; o < 32; o++) acc[o] = __ldg(mlp_b1 + 32*c + o);

    const float* wbase = mlp_w1 + (size_t)(32 * c) * 208;
    const float2* ab = g_allfeat2 + (size_t)b;

    #pragma unroll 1
    for (int dc = 0; dc < 52; dc++) {      // 4 scalar rows = 2 float2 rows
        float2 u = ab[(size_t)(2*dc)     * sB];
        float2 v = ab[(size_t)(2*dc + 1) * sB];
        float a0 = u.x, a1 = u.y, a2 = v.x, a3 = v.y;
        const float* wb = wbase + 4 * dc;
        #pragma unroll
        for (int o = 0; o < 32; o++) {
            float4 w = ldg4(wb + o * 208);
            acc[o] += w.x*a0 + w.y*a1 + w.z*a2 + w.w*a3;
        }
    }

    float2* hp = g_h12 + (size_t)(16 * c) * sB + (size_t)b;
    #pragma unroll
    for (int o = 0; o < 16; o++)
        hp[(size_t)o * sB] = make_float2(fmaxf(acc[2*o], 0.f),
                                         fmaxf(acc[2*o + 1], 0.f));
}

// ---------------------------------------------------------------------------
// k4: layers 2..4 + sigmoid.
// ---------------------------------------------------------------------------
extern "C" __global__ void __launch_bounds__(128, 4)
k4_out(const float* __restrict__ mlp_w2, const float* __restrict__ mlp_b2,
       const float* __restrict__ mlp_w3, const float* __restrict__ mlp_b3,
       const float* __restrict__ mlp_w4, const float* __restrict__ mlp_b4,
       float* __restrict__ out, int B)
{
    __shared__ float sW2[64 * 128];
    __shared__ float sW3[32 * 64];
    __shared__ float sW4[32];
    __shared__ float sB2[64];
    __shared__ float sB3[32];
    __shared__ float sB4s;

    for (int idx = threadIdx.x; idx < 64 * 128; idx += blockDim.x) sW2[idx] = mlp_w2[idx];
    for (int idx = threadIdx.x; idx < 32 * 64;  idx += blockDim.x) sW3[idx] = mlp_w3[idx];
    if (threadIdx.x < 64)  sB2[threadIdx.x] = mlp_b2[threadIdx.x];
    if (threadIdx.x < 32)  { sB3[threadIdx.x] = mlp_b3[threadIdx.x];
                             sW4[threadIdx.x] = mlp_w4[threadIdx.x]; }
    if (threadIdx.x == 0) sB4s = mlp_b4[0];
    __syncthreads();

    int b = blockIdx.x * blockDim.x + threadIdx.x;
    if (b >= B) return;
    size_t sB = (size_t)B;

    float acc2[64];
    #pragma unroll
    for (int o = 0; o < 64; o++) acc2[o] = sB2[o];

    const float2* hp = g_h12 + (size_t)b;
    #pragma unroll 1
    for (int kc = 0; kc < 32; kc++) {      // 4 scalar h1 rows = 2 float2 rows
        float2 u = hp[(size_t)(2*kc)     * sB];
        float2 v = hp[(size_t)(2*kc + 1) * sB];
        float a0 = u.x, a1 = u.y, a2 = v.x, a3 = v.y;
        const float* wb = sW2 + 4 * kc;
        #pragma unroll
        for (int o = 0; o < 64; o++) {
            float4 w = *(const float4*)(wb + o * 128);
            acc2[o] += w.x*a0 + w.y*a1 + w.z*a2 + w.w*a3;
        }
    }

    float h2l[64];
    #pragma unroll
    for (int o = 0; o < 64; o++) h2l[o] = fmaxf(acc2[o], 0.f);

    float acc3[32];
    #pragma unroll
    for (int o = 0; o < 32; o++) acc3[o] = sB3[o];
    #pragma unroll 1
    for (int kc = 0; kc < 16; kc++) {
        float a0 = h2l[4*kc+0], a1 = h2l[4*kc+1];
        float a2 = h2l[4*kc+2], a3 = h2l[4*kc+3];
        const float* wb = sW3 + 4 * kc;
        #pragma unroll
        for (int o = 0; o < 32; o++) {
            float4 w = *(const float4*)(wb + o * 64);
            acc3[o] += w.x*a0 + w.y*a1 + w.z*a2 + w.w*a3;
        }
    }

    float logit = sB4s;
    #pragma unroll
    for (int o = 0; o < 32; o++) logit += sW4[o] * fmaxf(acc3[o], 0.f);

    out[b] = 1.f / (1.f + expf(-logit));
}

// ---------------------------------------------------------------------------
extern "C" void kernel_launch(void* const* d_in, const int* in_sizes, int n_in,
                              void* d_out, int out_size)
{
    const int*   userid   = (const int*)d_in[0];
    const int*   itemid   = (const int*)d_in[1];
    const int*   user_age = (const int*)d_in[2];
    const int*   gender   = (const int*)d_in[3];
    const int*   user_occ = (const int*)d_in[4];
    const int*   item_kind= (const int*)d_in[5];
    const int*   his_id   = (const int*)d_in[6];
    const int*   his_kind = (const int*)d_in[7];
    const float* user_emb = (const float*)d_in[8];
    const float* item_emb = (const float*)d_in[9];
    const float* age_emb  = (const float*)d_in[10];
    const float* gen_emb  = (const float*)d_in[11];
    const float* occ_emb  = (const float*)d_in[12];
    const float* kind_emb = (const float*)d_in[13];
    const float* act_w1 = (const float*)d_in[14];
    const float* act_b1 = (const float*)d_in[15];
    const float* act_w2 = (const float*)d_in[16];
    const float* act_b2 = (const float*)d_in[17];
    const float* act_w3 = (const float*)d_in[18];
    const float* act_b3 = (const float*)d_in[19];
    const float* mlp_w1 = (const float*)d_in[20];
    const float* mlp_b1 = (const float*)d_in[21];
    const float* mlp_w2 = (const float*)d_in[22];
    const float* mlp_b2 = (const float*)d_in[23];
    const float* mlp_w3 = (const float*)d_in[24];
    const float* mlp_b3 = (const float*)d_in[25];
    const float* mlp_w4 = (const float*)d_in[26];
    const float* mlp_b4 = (const float*)d_in[27];

    int B = in_sizes[0];
    int nb = (B + 127) / 128;

    k0_feat<<<nb, 128>>>(userid, itemid, user_age, gender, user_occ, item_kind,
                         user_emb, item_emb, age_emb, gen_emb, occ_emb, kind_emb,
                         act_w1, act_b1, B);

    k1_score<<<dim3(nb, HIS), 128>>>(his_id, his_kind, item_emb, kind_emb,
                                     act_w1, act_w2, act_b2, act_w3, act_b3, B);

    k2_pool<<<nb, 128>>>(his_id, his_kind, item_emb, kind_emb, B);

    k3_h1<<<dim3(nb, 4), 128>>>(mlp_w1, mlp_b1, B);

    k4_out<<<nb, 128>>>(mlp_w2, mlp_b2, mlp_w3, mlp_b3, mlp_w4, mlp_b4,
                        (float*)d_out, B);
}

// round 8
// speedup vs baseline: 1.5151x; 1.0505x over previous
#include <cuda_runtime.h>
#include <math.h>

#define BMAX 65536
#define HIS 5
#define KINDS 10

// Compact transposed all_feat: 128 scalar rows (64 pairs):
//   rows 0..39  = user,item,age,gender,occ  (w1 cols 0..39)
//   rows 40..127 = his_pool (88)            (w1 cols 120..207)
static __device__ float2 g_allfeat2[64u * BMAX];
static __device__ float2 g_base2[32u * BMAX];      // 64 scalar rows
static __device__ float2 g_h12[64u * BMAX];        // 128 scalar rows
static __device__ float  g_score[HIS * BMAX];

// Precomputed tables (kk==0 rows are zero):
static __device__ float g_Wa0[64 * 8];             // (W1a+W1b)[:,0:8]
static __device__ float g_Wc0[64 * 8];             // (W1c-W1b)[:,0:8]
static __device__ float g_Ta[10 * 20 * 64];        // Wa kind chunks @ kind_emb
static __device__ float g_Tc[10 * 20 * 64];        // Wc kind chunks @ kind_emb
static __device__ float g_Tm[10 * 20 * 128];       // mlp_w1 cols 40..119 @ kind_emb

__device__ __forceinline__ float4 ldg4(const float* p) {
    return __ldg((const float4*)p);
}

// ---------------------------------------------------------------------------
// prep: build product tables. 52224 outputs total.
// ---------------------------------------------------------------------------
extern "C" __global__ void prep_tables(const float* __restrict__ act_w1,
                                       const float* __restrict__ mlp_w1,
                                       const float* __restrict__ kind_emb)
{
    int i = blockIdx.x * blockDim.x + threadIdx.x;
    // g_Wa0 / g_Wc0 : 1024 elems
    if (i < 1024) {
        int o = (i >> 3) & 63, d = i & 7;
        const float* r = act_w1 + o * 264;
        if (i < 512) g_Wa0[o * 8 + d] = r[d] + r[88 + d];
        else         g_Wc0[o * 8 + d] = r[176 + d] - r[88 + d];
        return;
    }
    i -= 1024;
    if (i < 12800 * 2) {     // Ta / Tc
        int which = i >= 12800;
        int t = which ? i - 12800 : i;
        int o = t & 63; t >>= 6;
        int kk = t % 20; int j = t / 20;   // j: chunk index 0..9 -> i1 dims 8(j+1)..
        float v = 0.f;
        if (kk != 0) {
            const float* r = act_w1 + o * 264 + 8 * (j + 1);
            const float* e = kind_emb + kk * 8;
            #pragma unroll
            for (int d = 0; d < 8; d++) {
                float w = which ? (r[176 + d] - r[88 + d]) : (r[d] + r[88 + d]);
                v += w * e[d];
            }
        }
        if (which) g_Tc[(j * 20 + kk) * 64 + o] = v;
        else       g_Ta[(j * 20 + kk) * 64 + o] = v;
        return;
    }
    i -= 25600;
    if (i < 25600) {         // Tm
        int o = i & 127; int t = i >> 7;
        int kk = t % 20; int j = t / 20;
        float v = 0.f;
        if (kk != 0) {
            const float* r = mlp_w1 + o * 208 + 40 + 8 * j;
            const float* e = kind_emb + kk * 8;
            #pragma unroll
            for (int d = 0; d < 8; d++) v += r[d] * e[d];
        }
        g_Tm[(j * 20 + kk) * 128 + o] = v;
    }
}

// ---------------------------------------------------------------------------
// k0: gathers (rows 0..39) + base = b1 + Wc0@item_w + sum_j Tc[j][kk].
// ---------------------------------------------------------------------------
extern "C" __global__ void __launch_bounds__(128, 4)
k0_feat(const int* __restrict__ userid, const int* __restrict__ itemid,
        const int* __restrict__ user_age, const int* __restrict__ gender,
        const int* __restrict__ user_occ, const int* __restrict__ item_kind,
        const float* __restrict__ user_emb, const float* __restrict__ item_emb,
        const float* __restrict__ age_emb, const float* __restrict__ gender_emb,
        const float* __restrict__ occ_emb,
        const float* __restrict__ act_b1, int B)
{
    __shared__ float sWc0[64 * 8];
    for (int idx = threadIdx.x; idx < 512; idx += blockDim.x) sWc0[idx] = g_Wc0[idx];
    __syncthreads();

    int b = blockIdx.x * blockDim.x + threadIdx.x;
    if (b >= B) return;
    size_t sB = (size_t)B;

    // gathers -> rows 0..39 (pairs 0..19)
    float4 iv0, iv1;
    {
        const float* p = user_emb + (size_t)userid[b] * 8;
        float4 a = ldg4(p), c = ldg4(p + 4);
        float2* q = g_allfeat2 + (size_t)b;
        q[0] = make_float2(a.x, a.y); q[sB] = make_float2(a.z, a.w);
        q[2*sB] = make_float2(c.x, c.y); q[3*sB] = make_float2(c.z, c.w);

        p = item_emb + (size_t)itemid[b] * 8;
        iv0 = ldg4(p); iv1 = ldg4(p + 4);
        q[4*sB] = make_float2(iv0.x, iv0.y); q[5*sB] = make_float2(iv0.z, iv0.w);
        q[6*sB] = make_float2(iv1.x, iv1.y); q[7*sB] = make_float2(iv1.z, iv1.w);

        p = age_emb + (size_t)user_age[b] * 8;
        a = ldg4(p); c = ldg4(p + 4);
        q[8*sB] = make_float2(a.x, a.y); q[9*sB] = make_float2(a.z, a.w);
        q[10*sB] = make_float2(c.x, c.y); q[11*sB] = make_float2(c.z, c.w);

        p = gender_emb + (size_t)gender[b] * 8;
        a = ldg4(p); c = ldg4(p + 4);
        q[12*sB] = make_float2(a.x, a.y); q[13*sB] = make_float2(a.z, a.w);
        q[14*sB] = make_float2(c.x, c.y); q[15*sB] = make_float2(c.z, c.w);

        p = occ_emb + (size_t)user_occ[b] * 8;
        a = ldg4(p); c = ldg4(p + 4);
        q[16*sB] = make_float2(a.x, a.y); q[17*sB] = make_float2(a.z, a.w);
        q[18*sB] = make_float2(c.x, c.y); q[19*sB] = make_float2(c.z, c.w);
    }

    float acc[64];
    #pragma unroll
    for (int o = 0; o < 64; o++) acc[o] = __ldg(act_b1 + o);

    // item chunk via Wc0 (smem)
    #pragma unroll
    for (int o = 0; o < 64; o++) {
        float4 w0 = *(const float4*)(sWc0 + o * 8);
        float4 w1 = *(const float4*)(sWc0 + o * 8 + 4);
        acc[o] += w0.x*iv0.x + w0.y*iv0.y + w0.z*iv0.z + w0.w*iv0.w
                + w1.x*iv1.x + w1.y*iv1.y + w1.z*iv1.z + w1.w*iv1.w;
    }

    // kind chunks via table
    #pragma unroll 1
    for (int j = 0; j < 10; j++) {
        int kk = item_kind[b * KINDS + j];
        const float* t = g_Tc + (j * 20 + kk) * 64;
        #pragma unroll
        for (int q4 = 0; q4 < 16; q4++) {
            float4 v = ldg4(t + 4 * q4);
            acc[4*q4+0] += v.x; acc[4*q4+1] += v.y;
            acc[4*q4+2] += v.z; acc[4*q4+3] += v.w;
        }
    }

    float2* bp = g_base2 + (size_t)b;
    #pragma unroll
    for (int o = 0; o < 32; o++)
        bp[(size_t)o * sB] = make_float2(acc[2*o], acc[2*o + 1]);
}

// ---------------------------------------------------------------------------
// k1s: all 5 attention scores in one kernel.
// ---------------------------------------------------------------------------
extern "C" __global__ void __launch_bounds__(128, 4)
k1s_score(const int* __restrict__ his_id, const int* __restrict__ his_kind,
          const float* __restrict__ item_emb,
          const float* __restrict__ act_w2, const float* __restrict__ act_b2,
          const float* __restrict__ act_w3, const float* __restrict__ act_b3,
          int B)
{
    __shared__ float sWa0[64 * 8];
    __shared__ float sW2[32 * 64];
    __shared__ float sB2[32];
    __shared__ float sW3[32];
    __shared__ float sB3s;

    for (int idx = threadIdx.x; idx < 512; idx += blockDim.x) sWa0[idx] = g_Wa0[idx];
    for (int idx = threadIdx.x; idx < 32 * 64; idx += blockDim.x) sW2[idx] = act_w2[idx];
    if (threadIdx.x < 32) { sB2[threadIdx.x] = act_b2[threadIdx.x];
                            sW3[threadIdx.x] = act_w3[threadIdx.x]; }
    if (threadIdx.x == 0) sB3s = act_b3[0];
    __syncthreads();

    int b = blockIdx.x * blockDim.x + threadIdx.x;
    if (b >= B) return;
    size_t sB = (size_t)B;

    #pragma unroll 1
    for (int s = 0; s < HIS; s++) {
        float acc[64];
        {
            const float2* bp = g_base2 + (size_t)b;
            #pragma unroll
            for (int o = 0; o < 32; o++) {
                float2 v = bp[(size_t)o * sB];
                acc[2*o] = v.x; acc[2*o + 1] = v.y;
            }
        }

        // item chunk
        {
            int hid = his_id[b * HIS + s];
            const float* p = item_emb + (size_t)hid * 8;
            float4 v0 = ldg4(p), v1 = ldg4(p + 4);
            #pragma unroll
            for (int o = 0; o < 64; o++) {
                float4 w0 = *(const float4*)(sWa0 + o * 8);
                float4 w1 = *(const float4*)(sWa0 + o * 8 + 4);
                acc[o] += w0.x*v0.x + w0.y*v0.y + w0.z*v0.z + w0.w*v0.w
                        + w1.x*v1.x + w1.y*v1.y + w1.z*v1.z + w1.w*v1.w;
            }
        }

        // kind chunks via table
        #pragma unroll 1
        for (int j = 0; j < 10; j++) {
            int kk = his_kind[(b * HIS + s) * KINDS + j];
            const float* t = g_Ta + (j * 20 + kk) * 64;
            #pragma unroll
            for (int q4 = 0; q4 < 16; q4++) {
                float4 v = ldg4(t + 4 * q4);
                acc[4*q4+0] += v.x; acc[4*q4+1] += v.y;
                acc[4*q4+2] += v.z; acc[4*q4+3] += v.w;
            }
        }

        float h1l[64];
        #pragma unroll
        for (int o = 0; o < 64; o++) h1l[o] = fmaxf(acc[o], 0.f);

        float acc2[32];
        #pragma unroll
        for (int o = 0; o < 32; o++) acc2[o] = sB2[o];
        #pragma unroll 1
        for (int kc = 0; kc < 16; kc++) {
            float a0 = h1l[4*kc+0], a1 = h1l[4*kc+1];
            float a2 = h1l[4*kc+2], a3 = h1l[4*kc+3];
            const float* wb = sW2 + 4 * kc;
            #pragma unroll
            for (int o = 0; o < 32; o++) {
                float4 w = *(const float4*)(wb + o * 64);
                acc2[o] += w.x*a0 + w.y*a1 + w.z*a2 + w.w*a3;
            }
        }
        float sc = sB3s;
        #pragma unroll
        for (int o = 0; o < 32; o++) sc += sW3[o] * fmaxf(acc2[o], 0.f);
        g_score[(size_t)s * sB + (size_t)b] = sc;
    }
}

// ---------------------------------------------------------------------------
// k2: his_pool -> compact rows 40..127 (pairs 20..63).
// ---------------------------------------------------------------------------
extern "C" __global__ void __launch_bounds__(128, 4)
k2_pool(const int* __restrict__ his_id, const int* __restrict__ his_kind,
        const float* __restrict__ item_emb, const float* __restrict__ kind_emb,
        int B)
{
    int b = blockIdx.x * blockDim.x + threadIdx.x;
    if (b >= B) return;
    size_t sB = (size_t)B;

    float poolL[88];
    #pragma unroll 1
    for (int d = 0; d < 88; d++) poolL[d] = 0.f;

    #pragma unroll 1
    for (int s = 0; s < HIS; s++) {
        float sc = g_score[(size_t)s * sB + (size_t)b];
        int hid = his_id[b * HIS + s];
        #pragma unroll 1
        for (int j = 0; j < 11; j++) {
            float4 v0, v1;
            if (j == 0) {
                const float* p = item_emb + (size_t)hid * 8;
                v0 = ldg4(p); v1 = ldg4(p + 4);
            } else {
                int kk = his_kind[(b * HIS + s) * KINDS + (j - 1)];
                const float* p = kind_emb + (size_t)kk * 8;
                v0 = ldg4(p); v1 = ldg4(p + 4);
                if (kk == 0) { v0 = make_float4(0.f,0.f,0.f,0.f); v1 = v0; }
            }
            int pp = j * 8;
            poolL[pp+0] += v0.x*v0.x*sc; poolL[pp+1] += v0.y*v0.y*sc;
            poolL[pp+2] += v0.z*v0.z*sc; poolL[pp+3] += v0.w*v0.w*sc;
            poolL[pp+4] += v1.x*v1.x*sc; poolL[pp+5] += v1.y*v1.y*sc;
            poolL[pp+6] += v1.z*v1.z*sc; poolL[pp+7] += v1.w*v1.w*sc;
        }
    }
    float2* p = g_allfeat2 + (size_t)20 * sB + (size_t)b;
    #pragma unroll 1
    for (int d = 0; d < 44; d++)
        p[(size_t)d * sB] = make_float2(poolL[2*d], poolL[2*d + 1]);
}

// ---------------------------------------------------------------------------
// k3: h1 = relu(w1 @ all_feat + b1). 2 samples/thread, 32-output chunks.
// Dense part: 128 compact rows; kind part via g_Tm table.
// ---------------------------------------------------------------------------
extern "C" __global__ void __launch_bounds__(128, 4)
k3_h1(const float* __restrict__ mlp_w1, const float* __restrict__ mlp_b1,
      const int* __restrict__ item_kind, int B)
{
    int t = blockIdx.x * blockDim.x + threadIdx.x;
    int b0 = 2 * t;
    if (b0 >= B) return;
    int c = blockIdx.y;                 // output rows [32c, 32c+32)
    size_t sB = (size_t)B;

    float acc0[32], acc1[32];
    #pragma unroll
    for (int o = 0; o < 32; o++) {
        float bi = __ldg(mlp_b1 + 32*c + o);
        acc0[o] = bi; acc1[o] = bi;
    }

    const float* wbase = mlp_w1 + (size_t)(32 * c) * 208;
    const float2* ab = g_allfeat2 + (size_t)b0;

    #pragma unroll 1
    for (int dc = 0; dc < 32; dc++) {
        // A0 = {r0[b0], r1[b0], r0[b0+1], r1[b0+1]}, rows 4dc..4dc+1
        float4 A0 = *(const float4*)(ab + (size_t)(2*dc) * sB);
        float4 A1 = *(const float4*)(ab + (size_t)(2*dc + 1) * sB);
        int col = (dc < 10) ? 4*dc : 4*dc + 80;
        const float* wb = wbase + col;
        #pragma unroll
        for (int o = 0; o < 32; o++) {
            float4 w = ldg4(wb + o * 208);
            acc0[o] += w.x*A0.x + w.y*A0.y + w.z*A1.x + w.w*A1.y;
            acc1[o] += w.x*A0.z + w.y*A0.w + w.z*A1.z + w.w*A1.w;
        }
    }

    // kind rows via table
    #pragma unroll 1
    for (int j = 0; j < 10; j++) {
        int ka = item_kind[b0 * KINDS + j];
        int kb = item_kind[(b0 + 1) * KINDS + j];
        const float* ta = g_Tm + (j * 20 + ka) * 128 + 32 * c;
        const float* tb = g_Tm + (j * 20 + kb) * 128 + 32 * c;
        #pragma unroll
        for (int q4 = 0; q4 < 8; q4++) {
            float4 va = ldg4(ta + 4 * q4);
            float4 vb = ldg4(tb + 4 * q4);
            acc0[4*q4+0] += va.x; acc0[4*q4+1] += va.y;
            acc0[4*q4+2] += va.z; acc0[4*q4+3] += va.w;
            acc1[4*q4+0] += vb.x; acc1[4*q4+1] += vb.y;
            acc1[4*q4+2] += vb.z; acc1[4*q4+3] += vb.w;
        }
    }

    float2* hp = g_h12 + (size_t)(16 * c) * sB + (size_t)b0;
    #pragma unroll
    for (int o = 0; o < 16; o++) {
        float4 v = make_float4(fmaxf(acc0[2*o], 0.f), fmaxf(acc0[2*o+1], 0.f),
                               fmaxf(acc1[2*o], 0.f), fmaxf(acc1[2*o+1], 0.f));
        *(float4*)(hp + (size_t)o * sB) = v;
    }
}

// ---------------------------------------------------------------------------
// k4: layers 2..4 + sigmoid.
// ---------------------------------------------------------------------------
extern "C" __global__ void __launch_bounds__(128, 4)
k4_out(const float* __restrict__ mlp_w2, const float* __restrict__ mlp_b2,
       const float* __restrict__ mlp_w3, const float* __restrict__ mlp_b3,
       const float* __restrict__ mlp_w4, const float* __restrict__ mlp_b4,
       float* __restrict__ out, int B)
{
    __shared__ float sW2[64 * 128];
    __shared__ float sW3[32 * 64];
    __shared__ float sW4[32];
    __shared__ float sB2[64];
    __shared__ float sB3[32];
    __shared__ float sB4s;

    for (int idx = threadIdx.x; idx < 64 * 128; idx += blockDim.x) sW2[idx] = mlp_w2[idx];
    for (int idx = threadIdx.x; idx < 32 * 64;  idx += blockDim.x) sW3[idx] = mlp_w3[idx];
    if (threadIdx.x < 64)  sB2[threadIdx.x] = mlp_b2[threadIdx.x];
    if (threadIdx.x < 32)  { sB3[threadIdx.x] = mlp_b3[threadIdx.x];
                             sW4[threadIdx.x] = mlp_w4[threadIdx.x]; }
    if (threadIdx.x == 0) sB4s = mlp_b4[0];
    __syncthreads();

    int b = blockIdx.x * blockDim.x + threadIdx.x;
    if (b >= B) return;
    size_t sB = (size_t)B;

    float acc2[64];
    #pragma unroll
    for (int o = 0; o < 64; o++) acc2[o] = sB2[o];

    const float2* hp = g_h12 + (size_t)b;
    #pragma unroll 1
    for (int kc = 0; kc < 32; kc++) {
        float2 u = hp[(size_t)(2*kc)     * sB];
        float2 v = hp[(size_t)(2*kc + 1) * sB];
        float a0 = u.x, a1 = u.y, a2 = v.x, a3 = v.y;
        const float* wb = sW2 + 4 * kc;
        #pragma unroll
        for (int o = 0; o < 64; o++) {
            float4 w = *(const float4*)(wb + o * 128);
            acc2[o] += w.x*a0 + w.y*a1 + w.z*a2 + w.w*a3;
        }
    }

    float h2l[64];
    #pragma unroll
    for (int o = 0; o < 64; o++) h2l[o] = fmaxf(acc2[o], 0.f);

    float acc3[32];
    #pragma unroll
    for (int o = 0; o < 32; o++) acc3[o] = sB3[o];
    #pragma unroll 1
    for (int kc = 0; kc < 16; kc++) {
        float a0 = h2l[4*kc+0], a1 = h2l[4*kc+1];
        float a2 = h2l[4*kc+2], a3 = h2l[4*kc+3];
        const float* wb = sW3 + 4 * kc;
        #pragma unroll
        for (int o = 0; o < 32; o++) {
            float4 w = *(const float4*)(wb + o * 64);
            acc3[o] += w.x*a0 + w.y*a1 + w.z*a2 + w.w*a3;
        }
    }

    float logit = sB4s;
    #pragma unroll
    for (int o = 0; o < 32; o++) logit += sW4[o] * fmaxf(acc3[o], 0.f);

    out[b] = 1.f / (1.f + expf(-logit));
}

// ---------------------------------------------------------------------------
extern "C" void kernel_launch(void* const* d_in, const int* in_sizes, int n_in,
                              void* d_out, int out_size)
{
    const int*   userid   = (const int*)d_in[0];
    const int*   itemid   = (const int*)d_in[1];
    const int*   user_age = (const int*)d_in[2];
    const int*   gender   = (const int*)d_in[3];
    const int*   user_occ = (const int*)d_in[4];
    const int*   item_kind= (const int*)d_in[5];
    const int*   his_id   = (const int*)d_in[6];
    const int*   his_kind = (const int*)d_in[7];
    const float* user_emb = (const float*)d_in[8];
    const float* item_emb = (const float*)d_in[9];
    const float* age_emb  = (const float*)d_in[10];
    const float* gen_emb  = (const float*)d_in[11];
    const float* occ_emb  = (const float*)d_in[12];
    const float* kind_emb = (const float*)d_in[13];
    const float* act_w1 = (const float*)d_in[14];
    const float* act_b1 = (const float*)d_in[15];
    const float* act_w2 = (const float*)d_in[16];
    const float* act_b2 = (const float*)d_in[17];
    const float* act_w3 = (const float*)d_in[18];
    const float* act_b3 = (const float*)d_in[19];
    const float* mlp_w1 = (const float*)d_in[20];
    const float* mlp_b1 = (const float*)d_in[21];
    const float* mlp_w2 = (const float*)d_in[22];
    const float* mlp_b2 = (const float*)d_in[23];
    const float* mlp_w3 = (const float*)d_in[24];
    const float* mlp_b3 = (const float*)d_in[25];
    const float* mlp_w4 = (const float*)d_in[26];
    const float* mlp_b4 = (const float*)d_in[27];

    int B = in_sizes[0];
    int nb = (B + 127) / 128;

    prep_tables<<<204, 256>>>(act_w1, mlp_w1, kind_emb);

    k0_feat<<<nb, 128>>>(userid, itemid, user_age, gender, user_occ, item_kind,
                         user_emb, item_emb, age_emb, gen_emb, occ_emb,
                         act_b1, B);

    k1s_score<<<nb, 128>>>(his_id, his_kind, item_emb,
                           act_w2, act_b2, act_w3, act_b3, B);

    k2_pool<<<nb, 128>>>(his_id, his_kind, item_emb, kind_emb, B);

    k3_h1<<<dim3((B/2 + 127) / 128, 4), 128>>>(mlp_w1, mlp_b1, item_kind, B);

    k4_out<<<nb, 128>>>(mlp_w2, mlp_b2, mlp_w3, mlp_b3, mlp_w4, mlp_b4,
                        (float*)d_out, B);
}

// round 9
// speedup vs baseline: 1.8812x; 1.2416x over previous
#include <cuda_runtime.h>
#include <math.h>

#define BMAX 65536
#define HIS 5
#define KINDS 10

// Compact transposed all_feat: 128 scalar rows (64 pairs):
//   rows 0..39   = user,item,age,gender,occ  (w1 cols 0..39)
//   rows 40..127 = his_pool (88)             (w1 cols 120..207)
static __device__ float2 g_allfeat2[64u * BMAX];
static __device__ float2 g_base2[32u * BMAX];      // 64 scalar rows
static __device__ float2 g_h12[64u * BMAX];        // 128 scalar rows
static __device__ float  g_score[HIS * BMAX];

// Precomputed (kk==0 rows zero). Layouts chosen for warp-gather locality:
// g_Tc: [j][o4][kk] float4  -> ((j*16+o4)*20+kk)
// g_Tm: [j][o4][kk] float4  -> ((j*32+o4)*20+kk)
static __device__ float g_Wc0[64 * 8];             // (W1c-W1b)[:,0:8]
static __device__ float g_Tc[10 * 16 * 20 * 4];
static __device__ float g_Tm[10 * 32 * 20 * 4];

__device__ __forceinline__ float4 ldg4(const float* p) {
    return __ldg((const float4*)p);
}

// ---------------------------------------------------------------------------
// prep: 1024 + 12800 + 25600 = 39424 outputs.
// ---------------------------------------------------------------------------
extern "C" __global__ void prep_tables(const float* __restrict__ act_w1,
                                       const float* __restrict__ mlp_w1,
                                       const float* __restrict__ kind_emb)
{
    int i = blockIdx.x * blockDim.x + threadIdx.x;
    if (i < 1024) {
        if (i < 512) return;           // (Wa0 no longer needed)
        int t = i - 512;
        int o = t >> 3, d = t & 7;
        const float* r = act_w1 + o * 264;
        g_Wc0[o * 8 + d] = r[176 + d] - r[88 + d];
        return;
    }
    i -= 1024;
    if (i < 12800) {                   // Tc
        int f = i & 3; int r1 = i >> 2;
        int kk = r1 % 20; r1 /= 20;
        int o4 = r1 % 16; int j = r1 / 16;
        int o = 4 * o4 + f;
        float v = 0.f;
        if (kk != 0) {
            const float* r = act_w1 + o * 264 + 8 * (j + 1);
            const float* e = kind_emb + kk * 8;
            #pragma unroll
            for (int d = 0; d < 8; d++)
                v += (r[176 + d] - r[88 + d]) * e[d];
        }
        g_Tc[i] = v;
        return;
    }
    i -= 12800;
    if (i < 25600) {                   // Tm
        int f = i & 3; int r1 = i >> 2;
        int kk = r1 % 20; r1 /= 20;
        int o4 = r1 % 32; int j = r1 / 32;
        int o = 4 * o4 + f;
        float v = 0.f;
        if (kk != 0) {
            const float* r = mlp_w1 + o * 208 + 40 + 8 * j;
            const float* e = kind_emb + kk * 8;
            #pragma unroll
            for (int d = 0; d < 8; d++) v += r[d] * e[d];
        }
        g_Tm[i] = v;
    }
}

// ---------------------------------------------------------------------------
// k0: gathers (rows 0..39) + base = b1 + Wc0@item_w + sum_j Tc[j][:,kk].
// ---------------------------------------------------------------------------
extern "C" __global__ void __launch_bounds__(128, 4)
k0_feat(const int* __restrict__ userid, const int* __restrict__ itemid,
        const int* __restrict__ user_age, const int* __restrict__ gender,
        const int* __restrict__ user_occ, const int* __restrict__ item_kind,
        const float* __restrict__ user_emb, const float* __restrict__ item_emb,
        const float* __restrict__ age_emb, const float* __restrict__ gender_emb,
        const float* __restrict__ occ_emb,
        const float* __restrict__ act_b1, int B)
{
    __shared__ float sWc0[64 * 8];
    for (int idx = threadIdx.x; idx < 512; idx += blockDim.x) sWc0[idx] = g_Wc0[idx];
    __syncthreads();

    int b = blockIdx.x * blockDim.x + threadIdx.x;
    if (b >= B) return;
    size_t sB = (size_t)B;

    float4 iv0, iv1;
    {
        const float* p = user_emb + (size_t)userid[b] * 8;
        float4 a = ldg4(p), c = ldg4(p + 4);
        float2* q = g_allfeat2 + (size_t)b;
        q[0] = make_float2(a.x, a.y); q[sB] = make_float2(a.z, a.w);
        q[2*sB] = make_float2(c.x, c.y); q[3*sB] = make_float2(c.z, c.w);

        p = item_emb + (size_t)itemid[b] * 8;
        iv0 = ldg4(p); iv1 = ldg4(p + 4);
        q[4*sB] = make_float2(iv0.x, iv0.y); q[5*sB] = make_float2(iv0.z, iv0.w);
        q[6*sB] = make_float2(iv1.x, iv1.y); q[7*sB] = make_float2(iv1.z, iv1.w);

        p = age_emb + (size_t)user_age[b] * 8;
        a = ldg4(p); c = ldg4(p + 4);
        q[8*sB] = make_float2(a.x, a.y); q[9*sB] = make_float2(a.z, a.w);
        q[10*sB] = make_float2(c.x, c.y); q[11*sB] = make_float2(c.z, c.w);

        p = gender_emb + (size_t)gender[b] * 8;
        a = ldg4(p); c = ldg4(p + 4);
        q[12*sB] = make_float2(a.x, a.y); q[13*sB] = make_float2(a.z, a.w);
        q[14*sB] = make_float2(c.x, c.y); q[15*sB] = make_float2(c.z, c.w);

        p = occ_emb + (size_t)user_occ[b] * 8;
        a = ldg4(p); c = ldg4(p + 4);
        q[16*sB] = make_float2(a.x, a.y); q[17*sB] = make_float2(a.z, a.w);
        q[18*sB] = make_float2(c.x, c.y); q[19*sB] = make_float2(c.z, c.w);
    }

    float acc[64];
    #pragma unroll
    for (int o = 0; o < 64; o++) acc[o] = __ldg(act_b1 + o);

    #pragma unroll
    for (int o = 0; o < 64; o++) {
        float4 w0 = *(const float4*)(sWc0 + o * 8);
        float4 w1 = *(const float4*)(sWc0 + o * 8 + 4);
        acc[o] += w0.x*iv0.x + w0.y*iv0.y + w0.z*iv0.z + w0.w*iv0.w
                + w1.x*iv1.x + w1.y*iv1.y + w1.z*iv1.z + w1.w*iv1.w;
    }

    #pragma unroll 1
    for (int j = 0; j < 10; j++) {
        int kk = item_kind[b * KINDS + j];
        const float4* t = (const float4*)g_Tc + (size_t)(j * 16) * 20 + kk;
        #pragma unroll
        for (int o4 = 0; o4 < 16; o4++) {
            float4 v = __ldg(t + o4 * 20);
            acc[4*o4+0] += v.x; acc[4*o4+1] += v.y;
            acc[4*o4+2] += v.z; acc[4*o4+3] += v.w;
        }
    }

    float2* bp = g_base2 + (size_t)b;
    #pragma unroll
    for (int o = 0; o < 32; o++)
        bp[(size_t)o * sB] = make_float2(acc[2*o], acc[2*o + 1]);
}

// ---------------------------------------------------------------------------
// k1s: all 5 attention scores; layer-1 FMA with smem-broadcast Wa.
// ---------------------------------------------------------------------------
extern "C" __global__ void __launch_bounds__(128, 4)
k1s_score(const int* __restrict__ his_id, const int* __restrict__ his_kind,
          const float* __restrict__ item_emb, const float* __restrict__ kind_emb,
          const float* __restrict__ act_w1,
          const float* __restrict__ act_w2, const float* __restrict__ act_b2,
          const float* __restrict__ act_w3, const float* __restrict__ act_b3,
          int B)
{
    __shared__ float sWa[64 * 88];     // W1[:,0:88] + W1[:,88:176]
    __shared__ float sW2[32 * 64];
    __shared__ float sB2[32];
    __shared__ float sW3[32];
    __shared__ float sB3s;

    for (int idx = threadIdx.x; idx < 64 * 88; idx += blockDim.x) {
        int o = idx / 88, k = idx - o * 88;
        const float* r = act_w1 + o * 264;
        sWa[idx] = r[k] + r[88 + k];
    }
    for (int idx = threadIdx.x; idx < 32 * 64; idx += blockDim.x) sW2[idx] = act_w2[idx];
    if (threadIdx.x < 32) { sB2[threadIdx.x] = act_b2[threadIdx.x];
                            sW3[threadIdx.x] = act_w3[threadIdx.x]; }
    if (threadIdx.x == 0) sB3s = act_b3[0];
    __syncthreads();

    int b = blockIdx.x * blockDim.x + threadIdx.x;
    if (b >= B) return;
    size_t sB = (size_t)B;

    #pragma unroll 1
    for (int s = 0; s < HIS; s++) {
        float acc[64];
        {
            const float2* bp = g_base2 + (size_t)b;
            #pragma unroll
            for (int o = 0; o < 32; o++) {
                float2 v = bp[(size_t)o * sB];
                acc[2*o] = v.x; acc[2*o + 1] = v.y;
            }
        }

        int hid = his_id[b * HIS + s];
        #pragma unroll 1
        for (int j = 0; j < 11; j++) {
            float4 v0, v1;
            if (j == 0) {
                const float* p = item_emb + (size_t)hid * 8;
                v0 = ldg4(p); v1 = ldg4(p + 4);
            } else {
                int kk = his_kind[(b * HIS + s) * KINDS + (j - 1)];
                const float* p = kind_emb + (size_t)kk * 8;
                v0 = ldg4(p); v1 = ldg4(p + 4);
                float m = (kk != 0) ? 1.f : 0.f;
                v0.x*=m; v0.y*=m; v0.z*=m; v0.w*=m;
                v1.x*=m; v1.y*=m; v1.z*=m; v1.w*=m;
            }
            const float* wb = sWa + j * 8;
            #pragma unroll
            for (int o = 0; o < 64; o++) {
                float4 w0 = *(const float4*)(wb + o * 88);
                float4 w1 = *(const float4*)(wb + o * 88 + 4);
                acc[o] += w0.x*v0.x + w0.y*v0.y + w0.z*v0.z + w0.w*v0.w
                        + w1.x*v1.x + w1.y*v1.y + w1.z*v1.z + w1.w*v1.w;
            }
        }

        // layer 2, fully unrolled so h1 stays in registers
        float acc2[32];
        #pragma unroll
        for (int o = 0; o < 32; o++) acc2[o] = sB2[o];
        #pragma unroll
        for (int kc = 0; kc < 16; kc++) {
            float a0 = fmaxf(acc[4*kc+0], 0.f);
            float a1 = fmaxf(acc[4*kc+1], 0.f);
            float a2 = fmaxf(acc[4*kc+2], 0.f);
            float a3 = fmaxf(acc[4*kc+3], 0.f);
            const float* wb = sW2 + 4 * kc;
            #pragma unroll
            for (int o = 0; o < 32; o++) {
                float4 w = *(const float4*)(wb + o * 64);
                acc2[o] += w.x*a0 + w.y*a1 + w.z*a2 + w.w*a3;
            }
        }
        float sc = sB3s;
        #pragma unroll
        for (int o = 0; o < 32; o++) sc += sW3[o] * fmaxf(acc2[o], 0.f);
        g_score[(size_t)s * sB + (size_t)b] = sc;
    }
}

// ---------------------------------------------------------------------------
// k2: his_pool -> compact rows 40..127. Chunk loop fully unrolled, branch-free
// masking, pool register-resident.
// ---------------------------------------------------------------------------
extern "C" __global__ void __launch_bounds__(128, 4)
k2_pool(const int* __restrict__ his_id, const int* __restrict__ his_kind,
        const float* __restrict__ item_emb, const float* __restrict__ kind_emb,
        int B)
{
    int b = blockIdx.x * blockDim.x + threadIdx.x;
    if (b >= B) return;
    size_t sB = (size_t)B;

    float poolL[88];
    #pragma unroll
    for (int d = 0; d < 88; d++) poolL[d] = 0.f;

    #pragma unroll 1
    for (int s = 0; s < HIS; s++) {
        float sc = g_score[(size_t)s * sB + (size_t)b];
        int hid = his_id[b * HIS + s];
        {
            const float* p = item_emb + (size_t)hid * 8;
            float4 v0 = ldg4(p), v1 = ldg4(p + 4);
            poolL[0] += v0.x*v0.x*sc; poolL[1] += v0.y*v0.y*sc;
            poolL[2] += v0.z*v0.z*sc; poolL[3] += v0.w*v0.w*sc;
            poolL[4] += v1.x*v1.x*sc; poolL[5] += v1.y*v1.y*sc;
            poolL[6] += v1.z*v1.z*sc; poolL[7] += v1.w*v1.w*sc;
        }
        #pragma unroll
        for (int j = 0; j < 10; j++) {
            int kk = his_kind[(b * HIS + s) * KINDS + j];
            const float* p = kind_emb + (size_t)kk * 8;
            float4 v0 = ldg4(p), v1 = ldg4(p + 4);
            float fm = (kk != 0) ? sc : 0.f;
            int pp = 8 + j * 8;
            poolL[pp+0] += v0.x*v0.x*fm; poolL[pp+1] += v0.y*v0.y*fm;
            poolL[pp+2] += v0.z*v0.z*fm; poolL[pp+3] += v0.w*v0.w*fm;
            poolL[pp+4] += v1.x*v1.x*fm; poolL[pp+5] += v1.y*v1.y*fm;
            poolL[pp+6] += v1.z*v1.z*fm; poolL[pp+7] += v1.w*v1.w*fm;
        }
    }
    float2* p = g_allfeat2 + (size_t)20 * sB + (size_t)b;
    #pragma unroll
    for (int d = 0; d < 44; d++)
        p[(size_t)d * sB] = make_float2(poolL[2*d], poolL[2*d + 1]);
}

// ---------------------------------------------------------------------------
// k3: h1 = relu(w1 @ all_feat + b1). 2 samples/thread, 32-output chunks,
// dense part 128 rows + kind part via locality-ordered g_Tm.
// ---------------------------------------------------------------------------
extern "C" __global__ void __launch_bounds__(128, 4)
k3_h1(const float* __restrict__ mlp_w1, const float* __restrict__ mlp_b1,
      const int* __restrict__ item_kind, int B)
{
    int t = blockIdx.x * blockDim.x + threadIdx.x;
    int b0 = 2 * t;
    if (b0 >= B) return;
    int c = blockIdx.y;
    size_t sB = (size_t)B;

    float acc0[32], acc1[32];
    #pragma unroll
    for (int o = 0; o < 32; o++) {
        float bi = __ldg(mlp_b1 + 32*c + o);
        acc0[o] = bi; acc1[o] = bi;
    }

    const float* wbase = mlp_w1 + (size_t)(32 * c) * 208;
    const float2* ab = g_allfeat2 + (size_t)b0;

    #pragma unroll 1
    for (int dc = 0; dc < 32; dc++) {
        float4 A0 = *(const float4*)(ab + (size_t)(2*dc) * sB);
        float4 A1 = *(const float4*)(ab + (size_t)(2*dc + 1) * sB);
        int col = (dc < 10) ? 4*dc : 4*dc + 80;
        const float* wb = wbase + col;
        #pragma unroll
        for (int o = 0; o < 32; o++) {
            float4 w = ldg4(wb + o * 208);
            acc0[o] += w.x*A0.x + w.y*A0.y + w.z*A1.x + w.w*A1.y;
            acc1[o] += w.x*A0.z + w.y*A0.w + w.z*A1.z + w.w*A1.w;
        }
    }

    #pragma unroll 1
    for (int j = 0; j < 10; j++) {
        int ka = item_kind[b0 * KINDS + j];
        int kb = item_kind[(b0 + 1) * KINDS + j];
        const float4* ta = (const float4*)g_Tm + (size_t)(j * 32 + 8 * c) * 20 + ka;
        const float4* tb = (const float4*)g_Tm + (size_t)(j * 32 + 8 * c) * 20 + kb;
        #pragma unroll
        for (int q4 = 0; q4 < 8; q4++) {
            float4 va = __ldg(ta + q4 * 20);
            float4 vb = __ldg(tb + q4 * 20);
            acc0[4*q4+0] += va.x; acc0[4*q4+1] += va.y;
            acc0[4*q4+2] += va.z; acc0[4*q4+3] += va.w;
            acc1[4*q4+0] += vb.x; acc1[4*q4+1] += vb.y;
            acc1[4*q4+2] += vb.z; acc1[4*q4+3] += vb.w;
        }
    }

    float2* hp = g_h12 + (size_t)(16 * c) * sB + (size_t)b0;
    #pragma unroll
    for (int o = 0; o < 16; o++) {
        float4 v = make_float4(fmaxf(acc0[2*o], 0.f), fmaxf(acc0[2*o+1], 0.f),
                               fmaxf(acc1[2*o], 0.f), fmaxf(acc1[2*o+1], 0.f));
        *(float4*)(hp + (size_t)o * sB) = v;
    }
}

// ---------------------------------------------------------------------------
// k4: layers 2..4 + sigmoid. Fully-unrolled consumers keep h2 in registers.
// ---------------------------------------------------------------------------
extern "C" __global__ void __launch_bounds__(128, 4)
k4_out(const float* __restrict__ mlp_w2, const float* __restrict__ mlp_b2,
       const float* __restrict__ mlp_w3, const float* __restrict__ mlp_b3,
       const float* __restrict__ mlp_w4, const float* __restrict__ mlp_b4,
       float* __restrict__ out, int B)
{
    __shared__ float sW2[64 * 128];
    __shared__ float sW3[32 * 64];
    __shared__ float sW4[32];
    __shared__ float sB2[64];
    __shared__ float sB3[32];
    __shared__ float sB4s;

    for (int idx = threadIdx.x; idx < 64 * 128; idx += blockDim.x) sW2[idx] = mlp_w2[idx];
    for (int idx = threadIdx.x; idx < 32 * 64;  idx += blockDim.x) sW3[idx] = mlp_w3[idx];
    if (threadIdx.x < 64)  sB2[threadIdx.x] = mlp_b2[threadIdx.x];
    if (threadIdx.x < 32)  { sB3[threadIdx.x] = mlp_b3[threadIdx.x];
                             sW4[threadIdx.x] = mlp_w4[threadIdx.x]; }
    if (threadIdx.x == 0) sB4s = mlp_b4[0];
    __syncthreads();

    int b = blockIdx.x * blockDim.x + threadIdx.x;
    if (b >= B) return;
    size_t sB = (size_t)B;

    float acc2[64];
    #pragma unroll
    for (int o = 0; o < 64; o++) acc2[o] = sB2[o];

    const float2* hp = g_h12 + (size_t)b;
    #pragma unroll 1
    for (int kc = 0; kc < 32; kc++) {
        float2 u = hp[(size_t)(2*kc)     * sB];
        float2 v = hp[(size_t)(2*kc + 1) * sB];
        float a0 = u.x, a1 = u.y, a2 = v.x, a3 = v.y;
        const float* wb = sW2 + 4 * kc;
        #pragma unroll
        for (int o = 0; o < 64; o++) {
            float4 w = *(const float4*)(wb + o * 128);
            acc2[o] += w.x*a0 + w.y*a1 + w.z*a2 + w.w*a3;
        }
    }

    float acc3[32];
    #pragma unroll
    for (int o = 0; o < 32; o++) acc3[o] = sB3[o];
    #pragma unroll
    for (int kc = 0; kc < 16; kc++) {
        float a0 = fmaxf(acc2[4*kc+0], 0.f);
        float a1 = fmaxf(acc2[4*kc+1], 0.f);
        float a2 = fmaxf(acc2[4*kc+2], 0.f);
        float a3 = fmaxf(acc2[4*kc+3], 0.f);
        const float* wb = sW3 + 4 * kc;
        #pragma unroll
        for (int o = 0; o < 32; o++) {
            float4 w = *(const float4*)(wb + o * 64);
            acc3[o] += w.x*a0 + w.y*a1 + w.z*a2 + w.w*a3;
        }
    }

    float logit = sB4s;
    #pragma unroll
    for (int o = 0; o < 32; o++) logit += sW4[o] * fmaxf(acc3[o], 0.f);

    out[b] = 1.f / (1.f + expf(-logit));
}

// ---------------------------------------------------------------------------
extern "C" void kernel_launch(void* const* d_in, const int* in_sizes, int n_in,
                              void* d_out, int out_size)
{
    const int*   userid   = (const int*)d_in[0];
    const int*   itemid   = (const int*)d_in[1];
    const int*   user_age = (const int*)d_in[2];
    const int*   gender   = (const int*)d_in[3];
    const int*   user_occ = (const int*)d_in[4];
    const int*   item_kind= (const int*)d_in[5];
    const int*   his_id   = (const int*)d_in[6];
    const int*   his_kind = (const int*)d_in[7];
    const float* user_emb = (const float*)d_in[8];
    const float* item_emb = (const float*)d_in[9];
    const float* age_emb  = (const float*)d_in[10];
    const float* gen_emb  = (const float*)d_in[11];
    const float* occ_emb  = (const float*)d_in[12];
    const float* kind_emb = (const float*)d_in[13];
    const float* act_w1 = (const float*)d_in[14];
    const float* act_b1 = (const float*)d_in[15];
    const float* act_w2 = (const float*)d_in[16];
    const float* act_b2 = (const float*)d_in[17];
    const float* act_w3 = (const float*)d_in[18];
    const float* act_b3 = (const float*)d_in[19];
    const float* mlp_w1 = (const float*)d_in[20];
    const float* mlp_b1 = (const float*)d_in[21];
    const float* mlp_w2 = (const float*)d_in[22];
    const float* mlp_b2 = (const float*)d_in[23];
    const float* mlp_w3 = (const float*)d_in[24];
    const float* mlp_b3 = (const float*)d_in[25];
    const float* mlp_w4 = (const float*)d_in[26];
    const float* mlp_b4 = (const float*)d_in[27];

    int B = in_sizes[0];
    int nb = (B + 127) / 128;

    prep_tables<<<154, 256>>>(act_w1, mlp_w1, kind_emb);

    k0_feat<<<nb, 128>>>(userid, itemid, user_age, gender, user_occ, item_kind,
                         user_emb, item_emb, age_emb, gen_emb, occ_emb,
                         act_b1, B);

    k1s_score<<<nb, 128>>>(his_id, his_kind, item_emb, kind_emb, act_w1,
                           act_w2, act_b2, act_w3, act_b3, B);

    k2_pool<<<nb, 128>>>(his_id, his_kind, item_emb, kind_emb, B);

    k3_h1<<<dim3((B/2 + 127) / 128, 4), 128>>>(mlp_w1, mlp_b1, item_kind, B);

    k4_out<<<nb, 128>>>(mlp_w2, mlp_b2, mlp_w3, mlp_b3, mlp_w4, mlp_b4,
                        (float*)d_out, B);
}